// round 2
// baseline (speedup 1.0000x reference)
#include <cuda_runtime.h>
#include <cuda_bf16.h>

// ---------------------------------------------------------------------------
// weighted_loss: graph neighbor-state count -> key histogram -> weighted CE
//
// Inputs (metadata order):
//   d_in[0] : out        float32 [N,2]
//   d_in[1] : x          int32   [N]      (binary 0/1)
//   d_in[2] : y          int32   [N]      (binary 0/1)
//   d_in[3] : edge_index int32   [2,E]    (row = ei[0:E], col = ei[E:2E])
// Output: scalar float32
//
// State contract across calls (graph replays): all __device__ globals are
// zero at module load; each call ends with a cleanup kernel that restores
// every touched global to zero, so every call sees identical initial state.
// ---------------------------------------------------------------------------

#define MAXN   200704                 // >= N=200000, multiple of 16
#define HSIZE  (1 << 19)              // 512K-entry histogram (2 MB, L2 resident)

__device__ unsigned int  g_cnt2[2 * MAXN];   // [2i] = s1 (#nbr x==0), [2i+1] = s0 (#nbr x==1)
__device__ int           g_hist[HSIZE];
__device__ unsigned char g_xbytes[MAXN];     // 0 if x==0, 4 if x==1  (byte offset)
__device__ double        g_acc[2];           // [0] = sum(w*nll), [1] = sum(w)

// ---------------------------------------------------------------------------
// x -> byte-offset table (0 or 4); also zero the accumulators for this call.
__global__ void xbyte_kernel(const int* __restrict__ x, int N) {
    int i = blockIdx.x * blockDim.x + threadIdx.x;
    if (i < N) g_xbytes[i] = (x[i] > 0) ? 4 : 0;
    if (i < 2) g_acc[i] = 0.0;
}

// Edge scatter: for each edge (r, c): ++g_cnt2[2r + (x[c]?1:0)]
// x byte-offset table lives entirely in shared memory (1 CTA per SM).
__global__ void __launch_bounds__(1024, 1) edge_kernel(const int* __restrict__ ei,
                                                       int N, int E) {
    extern __shared__ unsigned char sx[];
    // preload full x byte table (16B vectors)
    {
        const uint4* src = (const uint4*)g_xbytes;
        uint4* dst = (uint4*)sx;
        int nw = MAXN >> 4;
        for (int w = threadIdx.x; w < nw; w += blockDim.x) dst[w] = src[w];
    }
    __syncthreads();

    char* cnt_base = (char*)g_cnt2;
    const int4* row4 = (const int4*)ei;
    const int4* col4 = (const int4*)(ei + E);
    int n4 = E >> 2;
    int tid    = blockIdx.x * blockDim.x + threadIdx.x;
    int stride = gridDim.x * blockDim.x;

    for (int i = tid; i < n4; i += stride) {
        int4 r = row4[i];
        int4 c = col4[i];
        unsigned int b0 = sx[c.x];
        unsigned int b1 = sx[c.y];
        unsigned int b2 = sx[c.z];
        unsigned int b3 = sx[c.w];
        atomicAdd((unsigned int*)(cnt_base + (((size_t)(unsigned)r.x) << 3) + b0), 1u);
        atomicAdd((unsigned int*)(cnt_base + (((size_t)(unsigned)r.y) << 3) + b1), 1u);
        atomicAdd((unsigned int*)(cnt_base + (((size_t)(unsigned)r.z) << 3) + b2), 1u);
        atomicAdd((unsigned int*)(cnt_base + (((size_t)(unsigned)r.w) << 3) + b3), 1u);
    }
    // tail (E not multiple of 4)
    if (blockIdx.x == 0 && threadIdx.x == 0) {
        const int* rowp = ei;
        const int* colp = ei + E;
        for (int i = n4 << 2; i < E; i++) {
            int r = rowp[i], c = colp[i];
            atomicAdd((unsigned int*)(cnt_base + (((size_t)(unsigned)r) << 3) + sx[c]), 1u);
        }
    }
}

__device__ __forceinline__ int make_key(int xbyte, int s0, int s1) {
    if (s0 > 511) s0 = 511;     // degree ~ Poisson(64); never reached in practice
    if (s1 > 511) s1 = 511;
    return (xbyte ? (1 << 18) : 0) | (s0 << 9) | s1;
}

// Key histogram: 2 nodes per thread, vectorized count loads.
__global__ void hist_kernel(int N) {
    int t = blockIdx.x * blockDim.x + threadIdx.x;
    int i = t * 2;
    if (i + 1 < N) {
        int4 c = ((const int4*)g_cnt2)[t];      // nodes i (c.x=s1,c.y=s0), i+1 (c.z,c.w)
        unsigned char xb0 = g_xbytes[i];
        unsigned char xb1 = g_xbytes[i + 1];
        atomicAdd(&g_hist[make_key(xb0, c.y, c.x)], 1);
        atomicAdd(&g_hist[make_key(xb1, c.w, c.z)], 1);
    } else if (i < N) {
        int s1 = g_cnt2[2 * i], s0 = g_cnt2[2 * i + 1];
        atomicAdd(&g_hist[make_key(g_xbytes[i], s0, s1)], 1);
    }
}

__inline__ __device__ float warp_reduce(float v) {
    #pragma unroll
    for (int o = 16; o > 0; o >>= 1) v += __shfl_down_sync(0xFFFFFFFFu, v, o);
    return v;
}

// Weighted loss reduction: 2 nodes per thread.
__global__ void __launch_bounds__(256) node_kernel(const float* __restrict__ out2,
                                                   const int* __restrict__ y,
                                                   int N) {
    int tid    = blockIdx.x * blockDim.x + threadIdx.x;
    int stride = gridDim.x * blockDim.x;
    int n2 = N >> 1;
    float acc_wn = 0.0f, acc_w = 0.0f;

    for (int t = tid; t < n2; t += stride) {
        int i = t * 2;
        int4   c  = ((const int4*)g_cnt2)[t];
        float4 o  = ((const float4*)out2)[t];   // (o0,o1) node i, (o2,o3) node i+1
        int2   yv = ((const int2*)y)[t];

        {
            int cnt = g_hist[make_key(g_xbytes[i], c.y, c.x)];
            float w = rsqrtf((float)cnt);
            float m = fmaxf(o.x, o.y);
            float lse = m + __logf(__expf(o.x - m) + __expf(o.y - m));
            float nll = lse - ((yv.x > 0) ? o.y : o.x);
            acc_wn += nll * w;
            acc_w  += w;
        }
        {
            int cnt = g_hist[make_key(g_xbytes[i + 1], c.w, c.z)];
            float w = rsqrtf((float)cnt);
            float m = fmaxf(o.z, o.w);
            float lse = m + __logf(__expf(o.z - m) + __expf(o.w - m));
            float nll = lse - ((yv.y > 0) ? o.w : o.z);
            acc_wn += nll * w;
            acc_w  += w;
        }
    }
    // odd-N tail handled by thread 0
    if (tid == 0 && (N & 1)) {
        int i = N - 1;
        int s1 = g_cnt2[2 * i], s0 = g_cnt2[2 * i + 1];
        int cnt = g_hist[make_key(g_xbytes[i], s0, s1)];
        float w = rsqrtf((float)cnt);
        float o0 = out2[2 * i], o1 = out2[2 * i + 1];
        float m = fmaxf(o0, o1);
        float lse = m + __logf(__expf(o0 - m) + __expf(o1 - m));
        float nll = lse - ((y[i] > 0) ? o1 : o0);
        acc_wn += nll * w;
        acc_w  += w;
    }

    __shared__ float swn[8], sw[8];
    int lane = threadIdx.x & 31, wid = threadIdx.x >> 5;
    acc_wn = warp_reduce(acc_wn);
    acc_w  = warp_reduce(acc_w);
    if (lane == 0) { swn[wid] = acc_wn; sw[wid] = acc_w; }
    __syncthreads();
    if (wid == 0) {
        int nwarp = (blockDim.x + 31) >> 5;
        acc_wn = (lane < nwarp) ? swn[lane] : 0.0f;
        acc_w  = (lane < nwarp) ? sw[lane]  : 0.0f;
        acc_wn = warp_reduce(acc_wn);
        acc_w  = warp_reduce(acc_w);
        if (lane == 0) {
            atomicAdd(&g_acc[0], (double)acc_wn);
            atomicAdd(&g_acc[1], (double)acc_w);
        }
    }
}

__global__ void finalize_kernel(float* out) {
    out[0] = (float)(g_acc[0] / g_acc[1]);
}

// Restore all touched globals to zero (instead of wiping 2MB every call).
__global__ void cleanup_kernel(int N) {
    int t = blockIdx.x * blockDim.x + threadIdx.x;
    int i = t * 2;
    if (i + 1 < N) {
        int4 c = ((const int4*)g_cnt2)[t];
        g_hist[make_key(g_xbytes[i],     c.y, c.x)] = 0;
        g_hist[make_key(g_xbytes[i + 1], c.w, c.z)] = 0;
        ((int4*)g_cnt2)[t] = make_int4(0, 0, 0, 0);
    } else if (i < N) {
        int s1 = g_cnt2[2 * i], s0 = g_cnt2[2 * i + 1];
        g_hist[make_key(g_xbytes[i], s0, s1)] = 0;
        g_cnt2[2 * i] = 0;
        g_cnt2[2 * i + 1] = 0;
    }
}

// ---------------------------------------------------------------------------
extern "C" void kernel_launch(void* const* d_in, const int* in_sizes, int n_in,
                              void* d_out, int out_size) {
    const float* out2 = (const float*)d_in[0];
    const int*   x    = (const int*)d_in[1];
    const int*   y    = (const int*)d_in[2];
    const int*   ei   = (const int*)d_in[3];
    float* res = (float*)d_out;

    int N = in_sizes[1];
    int E = in_sizes[3] / 2;

    static int sms = 0;
    if (sms == 0) {
        cudaDeviceGetAttribute(&sms, cudaDevAttrMultiProcessorCount, 0);
        cudaFuncSetAttribute(edge_kernel,
                             cudaFuncAttributeMaxDynamicSharedMemorySize, MAXN);
    }

    // 1. x byte table + acc zero
    xbyte_kernel<<<(N + 255) / 256, 256>>>(x, N);

    // 2. edge scatter: 1 CTA/SM, full x table in smem
    edge_kernel<<<sms, 1024, MAXN>>>(ei, N, E);

    // 3. key histogram (2 nodes/thread)
    hist_kernel<<<(N / 2 + 255) / 256, 256>>>(N);

    // 4. weighted loss reduction
    node_kernel<<<512, 256>>>(out2, y, N);

    // 5. scalar
    finalize_kernel<<<1, 1>>>(res);

    // 6. restore globals to zero for the next call
    cleanup_kernel<<<(N / 2 + 255) / 256, 256>>>(N);
}

// round 3
// speedup vs baseline: 1.0817x; 1.0817x over previous
#include <cuda_runtime.h>
#include <cuda_bf16.h>
#include <stdint.h>

// ---------------------------------------------------------------------------
// weighted_loss: graph neighbor-state count -> key histogram -> weighted CE
//
// Inputs (metadata order):
//   d_in[0] : out        float32 [N,2]
//   d_in[1] : x          int32   [N]      (binary 0/1)
//   d_in[2] : y          int32   [N]      (binary 0/1)
//   d_in[3] : edge_index int32   [2,E]    (row = ei[0:E], col = ei[E:2E])
// Output: scalar float32
// ---------------------------------------------------------------------------

#define MAXN   200704                 // >= N=200000, multiple of 16
#define HSIZE  (1 << 19)              // 512K-entry histogram (2 MB, L2 resident)

__device__ unsigned int  g_cnt2[2 * MAXN];   // [2i] = s1 (#nbr x==0), [2i+1] = s0 (#nbr x==1)
__device__ int           g_hist[HSIZE];
__device__ unsigned char g_xbytes[MAXN];     // 0 if x==0, 4 if x==1  (byte offset)
__device__ double        g_acc[2];           // [0] = sum(w*nll), [1] = sum(w)
__device__ unsigned int  g_done;             // last-block ticket (reset each call)

// ---------------------------------------------------------------------------
// Zero all scratch + build x byte-offset table. One launch.
__global__ void init_kernel(const int* __restrict__ x, int N) {
    int i = blockIdx.x * blockDim.x + threadIdx.x;
    if (i < HSIZE)    g_hist[i] = 0;
    if (i < 2 * MAXN) g_cnt2[i] = 0u;
    if (i < N)        g_xbytes[i] = (x[i] > 0) ? 4 : 0;
    if (i == 0) { g_acc[0] = 0.0; g_acc[1] = 0.0; }
}

// Edge scatter: for each edge (r, c): ++g_cnt2[2r + (x[c]?1:0)]
// x byte-offset table in shared memory (196KB, 1 CTA/SM).
// REDs are sub-warp serialized: 8 predicated RED groups with 4 active lanes
// each, converting within-instruction wavefront replays (2.07 cyc/wf) into
// cross-instruction wavefronts (~1 cyc/wf).
__global__ void __launch_bounds__(1024, 1) edge_kernel(const int* __restrict__ ei,
                                                       int N, int E) {
    extern __shared__ unsigned char sx[];
    {
        const uint4* src = (const uint4*)g_xbytes;
        uint4* dst = (uint4*)sx;
        int nw = MAXN >> 4;
        for (int w = threadIdx.x; w < nw; w += blockDim.x) dst[w] = src[w];
    }
    __syncthreads();

    unsigned long long base = (unsigned long long)(uintptr_t)(void*)g_cnt2;
    const int4* row4 = (const int4*)ei;
    const int4* col4 = (const int4*)(ei + E);
    int n4 = E >> 2;
    int tid    = blockIdx.x * blockDim.x + threadIdx.x;
    int stride = gridDim.x * blockDim.x;
    int sub = (threadIdx.x & 31) >> 2;          // 0..7: serialization group

    for (int i = tid; i < n4; i += stride) {
        int4 r = row4[i];
        int4 c = col4[i];
        unsigned long long a0 = base + (((unsigned long long)(unsigned)r.x) << 3) + sx[c.x];
        unsigned long long a1 = base + (((unsigned long long)(unsigned)r.y) << 3) + sx[c.y];
        unsigned long long a2 = base + (((unsigned long long)(unsigned)r.z) << 3) + sx[c.z];
        unsigned long long a3 = base + (((unsigned long long)(unsigned)r.w) << 3) + sx[c.w];
        #pragma unroll
        for (int k = 0; k < 8; k++) {
            asm volatile(
                "{\n\t"
                ".reg .pred q;\n\t"
                "setp.eq.s32 q, %0, %1;\n\t"
                "@q red.global.add.u32 [%2], 1;\n\t"
                "@q red.global.add.u32 [%3], 1;\n\t"
                "@q red.global.add.u32 [%4], 1;\n\t"
                "@q red.global.add.u32 [%5], 1;\n\t"
                "}"
                :: "r"(sub), "r"(k), "l"(a0), "l"(a1), "l"(a2), "l"(a3)
                : "memory");
        }
    }
    // tail (E not multiple of 4)
    if (blockIdx.x == 0 && threadIdx.x == 0) {
        const int* rowp = ei;
        const int* colp = ei + E;
        for (int i = n4 << 2; i < E; i++) {
            int r = rowp[i], c = colp[i];
            atomicAdd((unsigned int*)(uintptr_t)(base + (((unsigned long long)(unsigned)r) << 3) + sx[c]), 1u);
        }
    }
}

__device__ __forceinline__ int make_key(int xbyte, int s0, int s1) {
    if (s0 > 511) s0 = 511;     // degree ~ Poisson(64); never reached in practice
    if (s1 > 511) s1 = 511;
    return (xbyte ? (1 << 18) : 0) | (s0 << 9) | s1;
}

// Key histogram: 2 nodes per thread, vectorized count loads.
__global__ void hist_kernel(int N) {
    int t = blockIdx.x * blockDim.x + threadIdx.x;
    int i = t * 2;
    if (i + 1 < N) {
        int4 c = ((const int4*)g_cnt2)[t];      // node i: (c.x=s1, c.y=s0); node i+1: (c.z, c.w)
        unsigned char xb0 = g_xbytes[i];
        unsigned char xb1 = g_xbytes[i + 1];
        atomicAdd(&g_hist[make_key(xb0, c.y, c.x)], 1);
        atomicAdd(&g_hist[make_key(xb1, c.w, c.z)], 1);
    } else if (i < N) {
        int s1 = g_cnt2[2 * i], s0 = g_cnt2[2 * i + 1];
        atomicAdd(&g_hist[make_key(g_xbytes[i], s0, s1)], 1);
    }
}

__inline__ __device__ float warp_reduce(float v) {
    #pragma unroll
    for (int o = 16; o > 0; o >>= 1) v += __shfl_down_sync(0xFFFFFFFFu, v, o);
    return v;
}

// Weighted loss reduction: 2 nodes per thread; last block writes the scalar.
__global__ void __launch_bounds__(256) node_kernel(const float* __restrict__ out2,
                                                   const int* __restrict__ y,
                                                   int N, float* __restrict__ res) {
    int tid    = blockIdx.x * blockDim.x + threadIdx.x;
    int stride = gridDim.x * blockDim.x;
    int n2 = N >> 1;
    float acc_wn = 0.0f, acc_w = 0.0f;

    for (int t = tid; t < n2; t += stride) {
        int i = t * 2;
        int4   c  = ((const int4*)g_cnt2)[t];
        float4 o  = ((const float4*)out2)[t];
        int2   yv = ((const int2*)y)[t];
        {
            int cnt = g_hist[make_key(g_xbytes[i], c.y, c.x)];
            float w = rsqrtf((float)cnt);
            float m = fmaxf(o.x, o.y);
            float lse = m + __logf(__expf(o.x - m) + __expf(o.y - m));
            acc_wn += (lse - ((yv.x > 0) ? o.y : o.x)) * w;
            acc_w  += w;
        }
        {
            int cnt = g_hist[make_key(g_xbytes[i + 1], c.w, c.z)];
            float w = rsqrtf((float)cnt);
            float m = fmaxf(o.z, o.w);
            float lse = m + __logf(__expf(o.z - m) + __expf(o.w - m));
            acc_wn += (lse - ((yv.y > 0) ? o.w : o.z)) * w;
            acc_w  += w;
        }
    }
    if (tid == 0 && (N & 1)) {
        int i = N - 1;
        int s1 = g_cnt2[2 * i], s0 = g_cnt2[2 * i + 1];
        int cnt = g_hist[make_key(g_xbytes[i], s0, s1)];
        float w = rsqrtf((float)cnt);
        float o0 = out2[2 * i], o1 = out2[2 * i + 1];
        float m = fmaxf(o0, o1);
        float lse = m + __logf(__expf(o0 - m) + __expf(o1 - m));
        acc_wn += (lse - ((y[i] > 0) ? o1 : o0)) * w;
        acc_w  += w;
    }

    __shared__ float swn[8], sw[8];
    int lane = threadIdx.x & 31, wid = threadIdx.x >> 5;
    acc_wn = warp_reduce(acc_wn);
    acc_w  = warp_reduce(acc_w);
    if (lane == 0) { swn[wid] = acc_wn; sw[wid] = acc_w; }
    __syncthreads();
    if (wid == 0) {
        int nwarp = (blockDim.x + 31) >> 5;
        acc_wn = (lane < nwarp) ? swn[lane] : 0.0f;
        acc_w  = (lane < nwarp) ? sw[lane]  : 0.0f;
        acc_wn = warp_reduce(acc_wn);
        acc_w  = warp_reduce(acc_w);
        if (lane == 0) {
            atomicAdd(&g_acc[0], (double)acc_wn);
            atomicAdd(&g_acc[1], (double)acc_w);
            __threadfence();
            unsigned int t = atomicAdd(&g_done, 1u);
            if (t == gridDim.x - 1) {
                g_done = 0u;                       // reset for next graph replay
                res[0] = (float)(g_acc[0] / g_acc[1]);
            }
        }
    }
}

// ---------------------------------------------------------------------------
extern "C" void kernel_launch(void* const* d_in, const int* in_sizes, int n_in,
                              void* d_out, int out_size) {
    const float* out2 = (const float*)d_in[0];
    const int*   x    = (const int*)d_in[1];
    const int*   y    = (const int*)d_in[2];
    const int*   ei   = (const int*)d_in[3];
    float* res = (float*)d_out;

    int N = in_sizes[1];
    int E = in_sizes[3] / 2;

    static int sms = 0;
    if (sms == 0) {
        cudaDeviceGetAttribute(&sms, cudaDevAttrMultiProcessorCount, 0);
        cudaFuncSetAttribute(edge_kernel,
                             cudaFuncAttributeMaxDynamicSharedMemorySize, MAXN);
    }

    // 1. zero scratch + x byte table
    init_kernel<<<HSIZE / 256, 256>>>(x, N);

    // 2. edge scatter: 1 CTA/SM, full x table in smem, sub-warp serialized REDs
    edge_kernel<<<sms, 1024, MAXN>>>(ei, N, E);

    // 3. key histogram (2 nodes/thread)
    hist_kernel<<<(N / 2 + 255) / 256, 256>>>(N);

    // 4. weighted loss reduction + fused finalize (last-block ticket)
    node_kernel<<<512, 256>>>(out2, y, N, res);
}